// round 6
// baseline (speedup 1.0000x reference)
#include <cuda_runtime.h>
#include <math.h>
#include <stdint.h>

#define NFEAT 64
#define DIM   256
#define NHEAD 8
#define HDIM  32
#define XS    260   // xs row stride
#define QS    36    // qzh row stride (q, then z)
#define ATS   68    // att row stride

// smem floats: xs 16640 | kt 2048 | qzh 2304 | vh 2048 | att 4352 | red 256
#define OFF_KT   (NFEAT*XS)            // 16640
#define OFF_QZH  (OFF_KT + 2048)       // 18688
#define OFF_VH   (OFF_QZH + NFEAT*QS)  // 20992
#define OFF_ATT  (OFF_VH + 2048)       // 23040
#define OFF_RED  (OFF_ATT + NFEAT*ATS) // 27392
#define SMEM_FLOATS (OFF_RED + 256)    // 27648 -> 110,592 B

typedef unsigned long long u64;

// ---- fp32x2 packed helpers (scores / z phases) ----
__device__ __forceinline__ void ffma2(u64& d, u64 a, u64 b) {
    asm("fma.rn.f32x2 %0, %1, %2, %0;" : "+l"(d) : "l"(a), "l"(b));
}
__device__ __forceinline__ u64 dup2(float v) {
    u64 r; asm("mov.b64 %0, {%1, %1};" : "=l"(r) : "f"(v)); return r;
}
__device__ __forceinline__ float2 unpk(u64 v) {
    float lo, hi; asm("mov.b64 {%0, %1}, %2;" : "=f"(lo), "=f"(hi) : "l"(v));
    return make_float2(lo, hi);
}

// ---- tf32 helpers ----
__device__ __forceinline__ uint32_t f2tf(float x) {
    uint32_t r; asm("cvt.rna.tf32.f32 %0, %1;" : "=r"(r) : "f"(x)); return r;
}
__device__ __forceinline__ void split_tf(float x, uint32_t& hi, uint32_t& lo) {
    hi = f2tf(x);
    lo = f2tf(x - __uint_as_float(hi));
}
__device__ __forceinline__ void mma_tf32(float4& d,
    uint32_t a0, uint32_t a1, uint32_t a2, uint32_t a3,
    uint32_t b0, uint32_t b1)
{
    asm("mma.sync.aligned.m16n8k8.row.col.f32.tf32.tf32.f32 "
        "{%0,%1,%2,%3}, {%4,%5,%6,%7}, {%8,%9}, {%0,%1,%2,%3};"
        : "+f"(d.x), "+f"(d.y), "+f"(d.z), "+f"(d.w)
        : "r"(a0), "r"(a1), "r"(a2), "r"(a3), "r"(b0), "r"(b1));
}

__global__ __launch_bounds__(256, 2)
void autoint_kernel(const float* __restrict__ x,
                    const float* __restrict__ Wq, const float* __restrict__ bq,
                    const float* __restrict__ Wk, const float* __restrict__ bk,
                    const float* __restrict__ Wv, const float* __restrict__ bv,
                    const float* __restrict__ W1, const float* __restrict__ b1,
                    const float* __restrict__ W2, const float* __restrict__ b2,
                    float* __restrict__ out)
{
    extern __shared__ float sm[];
    float* xs  = sm;
    float* kt  = sm + OFF_KT;    // [32 kcol][64 row]
    float* qzh = sm + OFF_QZH;   // [64][36]: q during proj/scores, z after
    float* vh  = sm + OFF_VH;    // [64][32]
    float* att = sm + OFF_ATT;   // [64][68]; aliased as weight scratch
    float* red = sm + OFF_RED;   // [256]
    uint32_t* wsc = (uint32_t*)att;   // weight scratch (tf32 bit patterns)

    const int t = threadIdx.x;
    const int b = blockIdx.x;
    const float* xg = x + (size_t)b * (NFEAT * DIM);

    // warp/lane decomposition for mma phases
    const int lane = t & 31;
    const int grp  = lane >> 2;     // 0..7
    const int tig  = lane & 3;      // 0..3
    const int w    = t >> 5;        // 0..7
    const int m0   = (w & 3) << 4;  // m-tile base row
    const int half = w >> 2;        // n-half

    // ---- load x ----
    {
        const float4* xg4 = (const float4*)xg;
#pragma unroll
        for (int n = t; n < NFEAT * DIM / 4; n += 256) {
            float4 v = xg4[n];
            *(float4*)&xs[(n >> 6) * XS + ((n & 63) << 2)] = v;
        }
    }
    __syncthreads();

    const float inv_sqrt_d = 0.17677669529663687f; // 1/sqrt(32)

    // persistent W1 accumulators: 16 n-tiles x 4 f32 (fragment layout)
    float4 facc4[16];
#pragma unroll
    for (int i = 0; i < 16; i++) facc4[i] = make_float4(0.f, 0.f, 0.f, 0.f);

    for (int h = 0; h < NHEAD; h++) {
        const int hd = h * HDIM;

        // ================= QKV projection via tf32 mma (3x split) =========
        // out[64 x 96] = X[64 x 256] @ [Wq|Wk|Wv][256, hd:hd+32]
        // warp tile: m16 x n48. 16 chunks of K=16 staged hi/lo transposed.
        float4 D[6];
#pragma unroll
        for (int i = 0; i < 6; i++) D[i] = make_float4(0.f, 0.f, 0.f, 0.f);

        for (int ch = 0; ch < 16; ch++) {
            __syncthreads();   // scratch free (prev compute / prev phase done)
            // ---- stage 16k x 96n, split hi/lo, transposed [n][k] stride 20
            if (t < 192) {
                const int kk  = t / 12;
                const int n8  = (t % 12) * 8;
                const int gk  = ch * 16 + kk;
                const int mat = n8 >> 5;
                const int col = hd + (n8 & 31);
                const float* W = (mat == 0) ? Wq : (mat == 1) ? Wk : Wv;
                float4 wa = *(const float4*)&W[gk * DIM + col];
                float4 wb = *(const float4*)&W[gk * DIM + col + 4];
                float wv8[8] = {wa.x, wa.y, wa.z, wa.w, wb.x, wb.y, wb.z, wb.w};
#pragma unroll
                for (int e = 0; e < 8; e++) {
                    uint32_t hi, lo;
                    split_tf(wv8[e], hi, lo);
                    wsc[(n8 + e) * 20 + kk]        = hi;
                    wsc[1920 + (n8 + e) * 20 + kk] = lo;
                }
            }
            __syncthreads();
            // ---- compute: 2 k-steps of 8
#pragma unroll
            for (int ks = 0; ks < 16; ks += 8) {
                const int k0 = ch * 16 + ks;
                uint32_t ah[4], al[4];
                split_tf(xs[(m0 + grp)     * XS + k0 + tig],     ah[0], al[0]);
                split_tf(xs[(m0 + grp + 8) * XS + k0 + tig],     ah[1], al[1]);
                split_tf(xs[(m0 + grp)     * XS + k0 + tig + 4], ah[2], al[2]);
                split_tf(xs[(m0 + grp + 8) * XS + k0 + tig + 4], ah[3], al[3]);
#pragma unroll
                for (int nt = 0; nt < 6; nt++) {
                    const int nb = half * 48 + nt * 8;
                    uint32_t bh0 = wsc[(nb + grp) * 20 + ks + tig];
                    uint32_t bh1 = wsc[(nb + grp) * 20 + ks + tig + 4];
                    uint32_t bl0 = wsc[1920 + (nb + grp) * 20 + ks + tig];
                    uint32_t bl1 = wsc[1920 + (nb + grp) * 20 + ks + tig + 4];
                    mma_tf32(D[nt], ah[0], ah[1], ah[2], ah[3], bh0, bh1);
                    mma_tf32(D[nt], al[0], al[1], al[2], al[3], bh0, bh1);
                    mma_tf32(D[nt], ah[0], ah[1], ah[2], ah[3], bl0, bl1);
                }
            }
        }
        // ---- scatter D + bias into qzh / kt / vh ----
        {
            const int r0 = m0 + grp, r1 = r0 + 8;
#pragma unroll
            for (int nt = 0; nt < 6; nt++) {
                const int n   = half * 48 + nt * 8 + 2 * tig;  // even, 0..94
                const int mat = n >> 5;
                const int mc  = n & 31;
                const float* bp = (mat == 0) ? bq : (mat == 1) ? bk : bv;
                float2 bb = *(const float2*)&bp[hd + mc];
                float4 d = D[nt];
                if (mat == 0) {
                    *(float2*)&qzh[r0 * QS + mc] = make_float2(d.x + bb.x, d.y + bb.y);
                    *(float2*)&qzh[r1 * QS + mc] = make_float2(d.z + bb.x, d.w + bb.y);
                } else if (mat == 1) {
                    kt[mc * 64 + r0]       = d.x + bb.x;
                    kt[(mc + 1) * 64 + r0] = d.y + bb.y;
                    kt[mc * 64 + r1]       = d.z + bb.x;
                    kt[(mc + 1) * 64 + r1] = d.w + bb.y;
                } else {
                    *(float2*)&vh[r0 * HDIM + mc] = make_float2(d.x + bb.x, d.y + bb.y);
                    *(float2*)&vh[r1 * HDIM + mc] = make_float2(d.z + bb.x, d.w + bb.y);
                }
            }
        }
        __syncthreads();

        // ================= scores (fp32x2): att = q.k^T / sqrt(d) =========
        {
            const int i0 = (t >> 4) << 2;
            const int j0 = (t & 15) << 2;
            u64 a[4][2];
#pragma unroll
            for (int r = 0; r < 4; r++) { a[r][0] = 0ull; a[r][1] = 0ull; }
#pragma unroll
            for (int kk = 0; kk < HDIM; kk += 4) {
                ulonglong2 k0 = *(const ulonglong2*)&kt[(kk+0)*64 + j0];
                ulonglong2 k1 = *(const ulonglong2*)&kt[(kk+1)*64 + j0];
                ulonglong2 k2 = *(const ulonglong2*)&kt[(kk+2)*64 + j0];
                ulonglong2 k3 = *(const ulonglong2*)&kt[(kk+3)*64 + j0];
                float4 q0 = *(const float4*)&qzh[(i0+0)*QS + kk];
                float4 q1 = *(const float4*)&qzh[(i0+1)*QS + kk];
                float4 q2 = *(const float4*)&qzh[(i0+2)*QS + kk];
                float4 q3 = *(const float4*)&qzh[(i0+3)*QS + kk];
#pragma unroll
                for (int r = 0; r < 4; r++) {
                    float4 qr = (r==0) ? q0 : (r==1) ? q1 : (r==2) ? q2 : q3;
                    u64 d;
                    d = dup2(qr.x); ffma2(a[r][0], d, k0.x); ffma2(a[r][1], d, k0.y);
                    d = dup2(qr.y); ffma2(a[r][0], d, k1.x); ffma2(a[r][1], d, k1.y);
                    d = dup2(qr.z); ffma2(a[r][0], d, k2.x); ffma2(a[r][1], d, k2.y);
                    d = dup2(qr.w); ffma2(a[r][0], d, k3.x); ffma2(a[r][1], d, k3.y);
                }
            }
#pragma unroll
            for (int r = 0; r < 4; r++) {
                float2 lo = unpk(a[r][0]);
                float2 hi = unpk(a[r][1]);
                *(float4*)&att[(i0+r)*ATS + j0] = make_float4(
                    lo.x*inv_sqrt_d, lo.y*inv_sqrt_d, hi.x*inv_sqrt_d, hi.y*inv_sqrt_d);
            }
        }
        __syncthreads();

        // ---- softmax: 2 threads per row ----
        if (t < 128) {
            const int row = t >> 1;
            const int hf  = (t & 1) << 5;
            float* rp = att + row * ATS + hf;
            float m = rp[0];
#pragma unroll
            for (int j = 1; j < 32; j++) m = fmaxf(m, rp[j]);
            m = fmaxf(m, __shfl_xor_sync(0xFFFFFFFF, m, 1));
            float s = 0.f;
#pragma unroll
            for (int j = 0; j < 32; j++) { float e = __expf(rp[j] - m); rp[j] = e; s += e; }
            s += __shfl_xor_sync(0xFFFFFFFF, s, 1);
            float inv = 1.f / s;
#pragma unroll
            for (int j = 0; j < 32; j++) rp[j] *= inv;
        }
        __syncthreads();

        // ================= z = att @ vh -> qzh (q is dead) ================
        {
            const int c4 = (t & 7) << 2;
            const int i0 = (t >> 3) << 1;
            u64 a0[2] = {0ull, 0ull};
            u64 a1[2] = {0ull, 0ull};
#pragma unroll 4
            for (int j = 0; j < NFEAT; j += 4) {
                float4 p0 = *(const float4*)&att[i0 * ATS + j];
                float4 p1 = *(const float4*)&att[(i0+1) * ATS + j];
                ulonglong2 v0 = *(const ulonglong2*)&vh[(j+0)*HDIM + c4];
                ulonglong2 v1 = *(const ulonglong2*)&vh[(j+1)*HDIM + c4];
                ulonglong2 v2 = *(const ulonglong2*)&vh[(j+2)*HDIM + c4];
                ulonglong2 v3 = *(const ulonglong2*)&vh[(j+3)*HDIM + c4];
                u64 d;
                d = dup2(p0.x); ffma2(a0[0], d, v0.x); ffma2(a0[1], d, v0.y);
                d = dup2(p0.y); ffma2(a0[0], d, v1.x); ffma2(a0[1], d, v1.y);
                d = dup2(p0.z); ffma2(a0[0], d, v2.x); ffma2(a0[1], d, v2.y);
                d = dup2(p0.w); ffma2(a0[0], d, v3.x); ffma2(a0[1], d, v3.y);
                d = dup2(p1.x); ffma2(a1[0], d, v0.x); ffma2(a1[1], d, v0.y);
                d = dup2(p1.y); ffma2(a1[0], d, v1.x); ffma2(a1[1], d, v1.y);
                d = dup2(p1.z); ffma2(a1[0], d, v2.x); ffma2(a1[1], d, v2.y);
                d = dup2(p1.w); ffma2(a1[0], d, v3.x); ffma2(a1[1], d, v3.y);
            }
            float2 a0lo = unpk(a0[0]), a0hi = unpk(a0[1]);
            float2 a1lo = unpk(a1[0]), a1hi = unpk(a1[1]);
            *(float4*)&qzh[i0 * QS + c4]     = make_float4(a0lo.x, a0lo.y, a0hi.x, a0hi.y);
            *(float4*)&qzh[(i0+1) * QS + c4] = make_float4(a1lo.x, a1lo.y, a1hi.x, a1hi.y);
        }
        __syncthreads();

        // ================= facc += z @ W1[hd:hd+32,:] via tf32 mma ========
        // M=64, N=256, K=32. 4 n-chunks of 64 staged hi/lo into att+red.
        for (int nc = 0; nc < 4; nc++) {
            // stage 32k x 64n transposed [n][k] stride 36 (att+red = 4608 fl)
            {
                const int kk = t >> 3;
                const int n8 = (t & 7) * 8;
                const float* src = W1 + (hd + kk) * DIM + nc * 64 + n8;
                float4 wa = *(const float4*)src;
                float4 wb = *(const float4*)(src + 4);
                float wv8[8] = {wa.x, wa.y, wa.z, wa.w, wb.x, wb.y, wb.z, wb.w};
                __syncthreads();   // prior readers of scratch done
#pragma unroll
                for (int e = 0; e < 8; e++) {
                    uint32_t hi, lo;
                    split_tf(wv8[e], hi, lo);
                    wsc[(n8 + e) * 36 + kk]        = hi;
                    wsc[2304 + (n8 + e) * 36 + kk] = lo;
                }
            }
            __syncthreads();
#pragma unroll
            for (int ks = 0; ks < 32; ks += 8) {
                uint32_t ah[4], al[4];
                split_tf(qzh[(m0 + grp)     * QS + ks + tig],     ah[0], al[0]);
                split_tf(qzh[(m0 + grp + 8) * QS + ks + tig],     ah[1], al[1]);
                split_tf(qzh[(m0 + grp)     * QS + ks + tig + 4], ah[2], al[2]);
                split_tf(qzh[(m0 + grp + 8) * QS + ks + tig + 4], ah[3], al[3]);
#pragma unroll
                for (int nt = 0; nt < 4; nt++) {
                    const int nl = half * 32 + nt * 8;
                    uint32_t bh0 = wsc[(nl + grp) * 36 + ks + tig];
                    uint32_t bh1 = wsc[(nl + grp) * 36 + ks + tig + 4];
                    uint32_t bl0 = wsc[2304 + (nl + grp) * 36 + ks + tig];
                    uint32_t bl1 = wsc[2304 + (nl + grp) * 36 + ks + tig + 4];
                    const int fi = nc * 4 + nt;
                    mma_tf32(facc4[fi], ah[0], ah[1], ah[2], ah[3], bh0, bh1);
                    mma_tf32(facc4[fi], al[0], al[1], al[2], al[3], bh0, bh1);
                    mma_tf32(facc4[fi], ah[0], ah[1], ah[2], ah[3], bl0, bl1);
                }
            }
            __syncthreads();
        }
        // loop to next head: first proj sync guards scratch reuse
    }

    // ================= epilogue: f = relu(facc + b1 + x); dot W2 ==========
    {
        const int r0 = m0 + grp, r1 = r0 + 8;
        float part = 0.f;
#pragma unroll
        for (int fi = 0; fi < 16; fi++) {
            const int n = (fi >> 2) * 64 + half * 32 + (fi & 3) * 8 + 2 * tig;
            float2 b1v = *(const float2*)&b1[n];
            float2 x0  = *(const float2*)&xs[r0 * XS + n];
            float2 x1  = *(const float2*)&xs[r1 * XS + n];
            float2 w20 = *(const float2*)&W2[r0 * DIM + n];
            float2 w21 = *(const float2*)&W2[r1 * DIM + n];
            float4 d = facc4[fi];
            float f0 = fmaxf(d.x + b1v.x + x0.x, 0.f);
            float f1 = fmaxf(d.y + b1v.y + x0.y, 0.f);
            float f2 = fmaxf(d.z + b1v.x + x1.x, 0.f);
            float f3 = fmaxf(d.w + b1v.y + x1.y, 0.f);
            part += f0 * w20.x + f1 * w20.y + f2 * w21.x + f3 * w21.y;
        }
        red[t] = part;
    }
    __syncthreads();

#pragma unroll
    for (int s = 128; s > 0; s >>= 1) {
        if (t < s) red[t] += red[t + s];
        __syncthreads();
    }
    if (t == 0) {
        out[b] = 1.f / (1.f + __expf(-(red[0] + b2[0])));
    }
}

extern "C" void kernel_launch(void* const* d_in, const int* in_sizes, int n_in,
                              void* d_out, int out_size)
{
    const float* x  = (const float*)d_in[0];
    const float* Wq = (const float*)d_in[1];
    const float* bq = (const float*)d_in[2];
    const float* Wk = (const float*)d_in[3];
    const float* bk = (const float*)d_in[4];
    const float* Wv = (const float*)d_in[5];
    const float* bv = (const float*)d_in[6];
    const float* W1 = (const float*)d_in[7];
    const float* b1 = (const float*)d_in[8];
    const float* W2 = (const float*)d_in[9];
    const float* b2 = (const float*)d_in[10];
    float* out = (float*)d_out;

    const int smem_bytes = SMEM_FLOATS * (int)sizeof(float); // 110,592 B
    cudaFuncSetAttribute(autoint_kernel,
                         cudaFuncAttributeMaxDynamicSharedMemorySize, smem_bytes);

    autoint_kernel<<<8192, 256, smem_bytes>>>(x, Wq, bq, Wk, bk, Wv, bv,
                                              W1, b1, W2, b2, out);
}

// round 7
// speedup vs baseline: 1.5187x; 1.5187x over previous
#include <cuda_runtime.h>
#include <math.h>
#include <stdint.h>

#define NFEAT 64
#define DIM   256
#define NHEAD 8
#define HDIM  32
#define QS    36    // qh row stride
#define ATS   68    // att row stride

// smem floats:
//  Axf  16384  (x in mma A-fragment order, fp32: [mt 4][ks 32][lane 32] float4)
//  kt    2048  (k transposed [32][64]; reused as z A-fragments [mt 4][ks 4][lane 32]f4)
//  qh    2304  ([64][36])
//  vh    2048  ([64][32])
//  att   4352  ([64][68]; aliased as tf32 B staging)
//  red    256
#define OFF_KT   16384
#define OFF_QH   (OFF_KT + 2048)
#define OFF_VH   (OFF_QH + NFEAT*QS)
#define OFF_ATT  (OFF_VH + 2048)
#define OFF_RED  (OFF_ATT + NFEAT*ATS)
#define SMEM_FLOATS (OFF_RED + 256)   // 27392 -> 109,568 B

typedef unsigned long long u64;

// ---- fp32x2 packed helpers (scores / z) ----
__device__ __forceinline__ void ffma2(u64& d, u64 a, u64 b) {
    asm("fma.rn.f32x2 %0, %1, %2, %0;" : "+l"(d) : "l"(a), "l"(b));
}
__device__ __forceinline__ u64 dup2(float v) {
    u64 r; asm("mov.b64 %0, {%1, %1};" : "=l"(r) : "f"(v)); return r;
}
__device__ __forceinline__ float2 unpk(u64 v) {
    float lo, hi; asm("mov.b64 {%0, %1}, %2;" : "=f"(lo), "=f"(hi) : "l"(v));
    return make_float2(lo, hi);
}

// ---- tf32 helpers ----
__device__ __forceinline__ uint32_t f2tf(float x) {
    uint32_t r; asm("cvt.rna.tf32.f32 %0, %1;" : "=r"(r) : "f"(x)); return r;
}
__device__ __forceinline__ void mma_tf32(float4& d,
    uint32_t a0, uint32_t a1, uint32_t a2, uint32_t a3,
    uint32_t b0, uint32_t b1)
{
    asm("mma.sync.aligned.m16n8k8.row.col.f32.tf32.tf32.f32 "
        "{%0,%1,%2,%3}, {%4,%5,%6,%7}, {%8,%9}, {%0,%1,%2,%3};"
        : "+f"(d.x), "+f"(d.y), "+f"(d.z), "+f"(d.w)
        : "r"(a0), "r"(a1), "r"(a2), "r"(a3), "r"(b0), "r"(b1));
}

__global__ __launch_bounds__(256, 2)
void autoint_kernel(const float* __restrict__ x,
                    const float* __restrict__ Wq, const float* __restrict__ bq,
                    const float* __restrict__ Wk, const float* __restrict__ bk,
                    const float* __restrict__ Wv, const float* __restrict__ bv,
                    const float* __restrict__ W1, const float* __restrict__ b1,
                    const float* __restrict__ W2, const float* __restrict__ b2,
                    float* __restrict__ out)
{
    extern __shared__ float sm[];
    float* axf = sm;
    float* kt  = sm + OFF_KT;
    float* qh  = sm + OFF_QH;
    float* vh  = sm + OFF_VH;
    float* att = sm + OFF_ATT;
    float* red = sm + OFF_RED;
    float* bst = att;                      // tf32 B staging alias
    uint32_t* bst_u = (uint32_t*)bst;
    uint32_t* kt_u  = (uint32_t*)kt;

    const int t = threadIdx.x;
    const int b = blockIdx.x;
    const float* xg = x + (size_t)b * (NFEAT * DIM);

    const int lane = t & 31;
    const int grp  = lane >> 2;
    const int tig  = lane & 3;
    const int w    = t >> 5;
    const int mt   = w & 3;          // m-tile (rows mt*16 .. +15)
    const int half = w >> 2;         // n-half

    // ---- phase 0: load x into A-fragment order (fp32) ----
    {
        const float4* xg4 = (const float4*)xg;
#pragma unroll
        for (int n = t; n < NFEAT * DIM / 4; n += 256) {
            float4 v = xg4[n];
            int r   = n >> 6;
            int c4  = (n & 63) << 2;
            int rmt = r >> 4, rgr = r & 7, hi8 = (r >> 3) & 1;
            int ks  = c4 >> 3, chi = (c4 >> 2) & 1;
            float* d = axf + (((rmt * 32 + ks) * 32 + rgr * 4) << 2) + hi8 + (chi << 1);
            d[0]  = v.x;  d[4]  = v.y;  d[8]  = v.z;  d[12] = v.w;
        }
    }
    __syncthreads();

    const float inv_sqrt_d = 0.17677669529663687f;

    float4 facc4[16];
#pragma unroll
    for (int i = 0; i < 16; i++) facc4[i] = make_float4(0.f, 0.f, 0.f, 0.f);

    for (int h = 0; h < NHEAD; h++) {
        const int hd = h * HDIM;

        // ===== QKV projection: [64x96] = X[64x256] @ [Wq|Wk|Wv][:,hd:hd+32]
        float4 D[6];
#pragma unroll
        for (int i = 0; i < 6; i++) D[i] = make_float4(0.f, 0.f, 0.f, 0.f);

        for (int ch = 0; ch < 16; ch++) {
            __syncthreads();            // bst free
            if (t < 192) {              // stage 16k x 96n tf32, fragment-paired
                int kk = t / 12;        // 0..15 (k within chunk)
                int ng = t % 12;        // n-tile 0..11
                int gk = ch * 16 + kk;
                int n8 = ng * 8;
                int mat = n8 >> 5;
                const float* W = (mat == 0) ? Wq : (mat == 1) ? Wk : Wv;
                int col = hd + (n8 & 31);
                float4 wa = *(const float4*)&W[gk * DIM + col];
                float4 wb = *(const float4*)&W[gk * DIM + col + 4];
                float wv8[8] = {wa.x, wa.y, wa.z, wa.w, wb.x, wb.y, wb.z, wb.w};
                int ksl = kk >> 3, tg = kk & 3, hi = (kk >> 2) & 1;
                uint32_t* dst = bst_u + (((ksl * 12 + ng) * 32) << 1) + tg * 2 + hi;
#pragma unroll
                for (int e = 0; e < 8; e++) dst[e * 8] = f2tf(wv8[e]);
            }
            __syncthreads();
#pragma unroll
            for (int ks2 = 0; ks2 < 2; ks2++) {
                float4 av = *(const float4*)&axf[(((mt * 32 + ch * 2 + ks2) * 32 + lane)) << 2];
                uint32_t a0 = f2tf(av.x), a1 = f2tf(av.y), a2 = f2tf(av.z), a3 = f2tf(av.w);
#pragma unroll
                for (int nt = 0; nt < 6; nt++) {
                    int ntg = half * 6 + nt;
                    uint2 bb = *(const uint2*)&bst_u[(((ks2 * 12 + ntg) * 32 + lane)) << 1];
                    mma_tf32(D[nt], a0, a1, a2, a3, bb.x, bb.y);
                }
            }
        }
        // scatter D + bias into qh / kt / vh
        {
            const int r0 = mt * 16 + grp, r1 = r0 + 8;
#pragma unroll
            for (int nt = 0; nt < 6; nt++) {
                const int n   = half * 48 + nt * 8 + 2 * tig;
                const int mat = n >> 5;
                const int mc  = n & 31;
                const float* bp = (mat == 0) ? bq : (mat == 1) ? bk : bv;
                float2 bb = *(const float2*)&bp[hd + mc];
                float4 d = D[nt];
                if (mat == 0) {
                    *(float2*)&qh[r0 * QS + mc] = make_float2(d.x + bb.x, d.y + bb.y);
                    *(float2*)&qh[r1 * QS + mc] = make_float2(d.z + bb.x, d.w + bb.y);
                } else if (mat == 1) {
                    kt[mc * 64 + r0]       = d.x + bb.x;
                    kt[(mc + 1) * 64 + r0] = d.y + bb.y;
                    kt[mc * 64 + r1]       = d.z + bb.x;
                    kt[(mc + 1) * 64 + r1] = d.w + bb.y;
                } else {
                    *(float2*)&vh[r0 * HDIM + mc] = make_float2(d.x + bb.x, d.y + bb.y);
                    *(float2*)&vh[r1 * HDIM + mc] = make_float2(d.z + bb.x, d.w + bb.y);
                }
            }
        }
        __syncthreads();

        // ===== scores (fp32x2): att = q.k^T / sqrt(d)
        {
            const int i0 = (t >> 4) << 2;
            const int j0 = (t & 15) << 2;
            u64 a[4][2];
#pragma unroll
            for (int r = 0; r < 4; r++) { a[r][0] = 0ull; a[r][1] = 0ull; }
#pragma unroll
            for (int kk = 0; kk < HDIM; kk += 4) {
                ulonglong2 k0 = *(const ulonglong2*)&kt[(kk+0)*64 + j0];
                ulonglong2 k1 = *(const ulonglong2*)&kt[(kk+1)*64 + j0];
                ulonglong2 k2 = *(const ulonglong2*)&kt[(kk+2)*64 + j0];
                ulonglong2 k3 = *(const ulonglong2*)&kt[(kk+3)*64 + j0];
                float4 q0 = *(const float4*)&qh[(i0+0)*QS + kk];
                float4 q1 = *(const float4*)&qh[(i0+1)*QS + kk];
                float4 q2 = *(const float4*)&qh[(i0+2)*QS + kk];
                float4 q3 = *(const float4*)&qh[(i0+3)*QS + kk];
#pragma unroll
                for (int r = 0; r < 4; r++) {
                    float4 qr = (r==0) ? q0 : (r==1) ? q1 : (r==2) ? q2 : q3;
                    u64 d;
                    d = dup2(qr.x); ffma2(a[r][0], d, k0.x); ffma2(a[r][1], d, k0.y);
                    d = dup2(qr.y); ffma2(a[r][0], d, k1.x); ffma2(a[r][1], d, k1.y);
                    d = dup2(qr.z); ffma2(a[r][0], d, k2.x); ffma2(a[r][1], d, k2.y);
                    d = dup2(qr.w); ffma2(a[r][0], d, k3.x); ffma2(a[r][1], d, k3.y);
                }
            }
#pragma unroll
            for (int r = 0; r < 4; r++) {
                float2 lo = unpk(a[r][0]);
                float2 hi = unpk(a[r][1]);
                *(float4*)&att[(i0+r)*ATS + j0] = make_float4(
                    lo.x*inv_sqrt_d, lo.y*inv_sqrt_d, hi.x*inv_sqrt_d, hi.y*inv_sqrt_d);
            }
        }
        __syncthreads();

        // ---- softmax: 2 threads per row ----
        if (t < 128) {
            const int row = t >> 1;
            const int hf  = (t & 1) << 5;
            float* rp = att + row * ATS + hf;
            float m = rp[0];
#pragma unroll
            for (int j = 1; j < 32; j++) m = fmaxf(m, rp[j]);
            m = fmaxf(m, __shfl_xor_sync(0xFFFFFFFF, m, 1));
            float s = 0.f;
#pragma unroll
            for (int j = 0; j < 32; j++) { float e = __expf(rp[j] - m); rp[j] = e; s += e; }
            s += __shfl_xor_sync(0xFFFFFFFF, s, 1);
            float inv = 1.f / s;
#pragma unroll
            for (int j = 0; j < 32; j++) rp[j] *= inv;
        }
        __syncthreads();

        // ===== z = att @ vh  ->  kt as tf32 A-fragments for W1
        {
            const int c4 = (t & 7) << 2;
            const int i0 = (t >> 3) << 1;
            u64 a0[2] = {0ull, 0ull};
            u64 a1[2] = {0ull, 0ull};
#pragma unroll 4
            for (int j = 0; j < NFEAT; j += 4) {
                float4 p0 = *(const float4*)&att[i0 * ATS + j];
                float4 p1 = *(const float4*)&att[(i0+1) * ATS + j];
                ulonglong2 v0 = *(const ulonglong2*)&vh[(j+0)*HDIM + c4];
                ulonglong2 v1 = *(const ulonglong2*)&vh[(j+1)*HDIM + c4];
                ulonglong2 v2 = *(const ulonglong2*)&vh[(j+2)*HDIM + c4];
                ulonglong2 v3 = *(const ulonglong2*)&vh[(j+3)*HDIM + c4];
                u64 d;
                d = dup2(p0.x); ffma2(a0[0], d, v0.x); ffma2(a0[1], d, v0.y);
                d = dup2(p0.y); ffma2(a0[0], d, v1.x); ffma2(a0[1], d, v1.y);
                d = dup2(p0.z); ffma2(a0[0], d, v2.x); ffma2(a0[1], d, v2.y);
                d = dup2(p0.w); ffma2(a0[0], d, v3.x); ffma2(a0[1], d, v3.y);
                d = dup2(p1.x); ffma2(a1[0], d, v0.x); ffma2(a1[1], d, v0.y);
                d = dup2(p1.y); ffma2(a1[0], d, v1.x); ffma2(a1[1], d, v1.y);
                d = dup2(p1.z); ffma2(a1[0], d, v2.x); ffma2(a1[1], d, v2.y);
                d = dup2(p1.w); ffma2(a1[0], d, v3.x); ffma2(a1[1], d, v3.y);
            }
            float2 a0lo = unpk(a0[0]), a0hi = unpk(a0[1]);
            float2 a1lo = unpk(a1[0]), a1hi = unpk(a1[1]);
            float vals[2][4] = {{a0lo.x, a0lo.y, a0hi.x, a0hi.y},
                                {a1lo.x, a1lo.y, a1hi.x, a1hi.y}};
#pragma unroll
            for (int rr = 0; rr < 2; rr++) {
                int r   = i0 + rr;
                int rmt = r >> 4, rgr = r & 7, hi8 = (r >> 3) & 1;
#pragma unroll
                for (int e = 0; e < 4; e++) {
                    int c  = c4 + e;
                    int ks = c >> 3, tg = c & 3, chi = (c >> 2) & 1;
                    kt_u[(((rmt * 4 + ks) * 32 + rgr * 4 + tg) << 2) + hi8 + (chi << 1)]
                        = f2tf(vals[rr][e]);
                }
            }
        }

        // ===== facc += z @ W1[hd:hd+32,:]  (tf32 mma, N in 2 chunks of 128)
        for (int nc = 0; nc < 2; nc++) {
            __syncthreads();   // nc=0: z fragments visible + bst free; nc=1: compute done
#pragma unroll
            for (int s = 0; s < 2; s++) {      // stage 32k x 128n
                int g  = t + s * 256;
                int kk = g >> 4;
                int ng = g & 15;
                int n  = nc * 128 + ng * 8;
                float4 wa = *(const float4*)&W1[(hd + kk) * DIM + n];
                float4 wb = *(const float4*)&W1[(hd + kk) * DIM + n + 4];
                float wv8[8] = {wa.x, wa.y, wa.z, wa.w, wb.x, wb.y, wb.z, wb.w};
                int ksl = kk >> 3, tg = kk & 3, hi = (kk >> 2) & 1;
                uint32_t* dst = bst_u + (((ksl * 16 + ng) * 32) << 1) + tg * 2 + hi;
#pragma unroll
                for (int e = 0; e < 8; e++) dst[e * 8] = f2tf(wv8[e]);
            }
            __syncthreads();
#pragma unroll
            for (int ks = 0; ks < 4; ks++) {
                uint4 za = *(const uint4*)&kt_u[(((mt * 4 + ks) * 32 + lane)) << 2];
#pragma unroll
                for (int nt = 0; nt < 8; nt++) {
                    int ntg = half * 8 + nt;
                    uint2 bb = *(const uint2*)&bst_u[(((ks * 16 + ntg) * 32 + lane)) << 1];
                    mma_tf32(facc4[nc * 8 + nt], za.x, za.y, za.z, za.w, bb.x, bb.y);
                }
            }
        }
        __syncthreads();   // protect kt/qh/vh/bst before next head
    }

    // ===== epilogue: f = relu(facc + b1 + x); dot W2 =====
    {
        const int r0 = mt * 16 + grp, r1 = r0 + 8;
        float part = 0.f;
#pragma unroll
        for (int fi = 0; fi < 16; fi++) {
            int nc = fi >> 3, nt = fi & 7;
            int n  = nc * 128 + half * 64 + nt * 8 + 2 * tig;
            float2 b1v = *(const float2*)&b1[n];
            int ksa = n >> 3;
            int tga = n & 3, chia = (n >> 2) & 1;
            int tgb = (n + 1) & 3, chib = ((n + 1) >> 2) & 1;
            const float* pa = &axf[(((mt * 32 + ksa) * 32 + grp * 4 + tga)) << 2];
            const float* pb = &axf[(((mt * 32 + ksa) * 32 + grp * 4 + tgb)) << 2];
            float x00 = pa[(chia << 1)];     // (r0, n)
            float x10 = pa[(chia << 1) + 1]; // (r1, n)
            float x01 = pb[(chib << 1)];     // (r0, n+1)
            float x11 = pb[(chib << 1) + 1]; // (r1, n+1)
            float2 w20 = *(const float2*)&W2[r0 * DIM + n];
            float2 w21 = *(const float2*)&W2[r1 * DIM + n];
            float4 d = facc4[fi];
            float f0 = fmaxf(d.x + b1v.x + x00, 0.f);
            float f1 = fmaxf(d.y + b1v.y + x01, 0.f);
            float f2 = fmaxf(d.z + b1v.x + x10, 0.f);
            float f3 = fmaxf(d.w + b1v.y + x11, 0.f);
            part += f0 * w20.x + f1 * w20.y + f2 * w21.x + f3 * w21.y;
        }
        red[t] = part;
    }
    __syncthreads();

#pragma unroll
    for (int s = 128; s > 0; s >>= 1) {
        if (t < s) red[t] += red[t + s];
        __syncthreads();
    }
    if (t == 0) {
        out[b] = 1.f / (1.f + __expf(-(red[0] + b2[0])));
    }
}

extern "C" void kernel_launch(void* const* d_in, const int* in_sizes, int n_in,
                              void* d_out, int out_size)
{
    const float* x  = (const float*)d_in[0];
    const float* Wq = (const float*)d_in[1];
    const float* bq = (const float*)d_in[2];
    const float* Wk = (const float*)d_in[3];
    const float* bk = (const float*)d_in[4];
    const float* Wv = (const float*)d_in[5];
    const float* bv = (const float*)d_in[6];
    const float* W1 = (const float*)d_in[7];
    const float* b1 = (const float*)d_in[8];
    const float* W2 = (const float*)d_in[9];
    const float* b2 = (const float*)d_in[10];
    float* out = (float*)d_out;

    const int smem_bytes = SMEM_FLOATS * (int)sizeof(float); // 109,568 B -> 2 CTAs/SM
    cudaFuncSetAttribute(autoint_kernel,
                         cudaFuncAttributeMaxDynamicSharedMemorySize, smem_bytes);

    autoint_kernel<<<8192, 256, smem_bytes>>>(x, Wq, bq, Wk, bk, Wv, bv,
                                              W1, b1, W2, b2, out);
}

// round 8
// speedup vs baseline: 2.6707x; 1.7585x over previous
#include <cuda_runtime.h>
#include <math.h>
#include <stdint.h>

#define NFEAT 64
#define DIM   256
#define NHEAD 8
#define HDIM  32
#define QS    36    // qh row stride
#define ATS   68    // att row stride

// smem floats:
//  Axf  16384  (x in mma A-fragment order, fp32)
//  kt    2048  (k transposed [32][64]; reused as z tf32 A-fragments)
//  qh    2304
//  vh    2048
//  att   4352  ([64][68]; aliased as tf32 B staging)
//  red    256
#define OFF_KT   16384
#define OFF_QH   (OFF_KT + 2048)
#define OFF_VH   (OFF_QH + NFEAT*QS)
#define OFF_ATT  (OFF_VH + 2048)
#define OFF_RED  (OFF_ATT + NFEAT*ATS)
#define SMEM_FLOATS (OFF_RED + 256)   // 27392 -> 109,568 B

typedef unsigned long long u64;

// ---- fp32x2 packed helpers ----
__device__ __forceinline__ void ffma2(u64& d, u64 a, u64 b) {
    asm("fma.rn.f32x2 %0, %1, %2, %0;" : "+l"(d) : "l"(a), "l"(b));
}
__device__ __forceinline__ u64 dup2(float v) {
    u64 r; asm("mov.b64 %0, {%1, %1};" : "=l"(r) : "f"(v)); return r;
}
__device__ __forceinline__ float2 unpk(u64 v) {
    float lo, hi; asm("mov.b64 {%0, %1}, %2;" : "=f"(lo), "=f"(hi) : "l"(v));
    return make_float2(lo, hi);
}

// ---- tf32 helpers ----
__device__ __forceinline__ uint32_t f2tf(float x) {
    uint32_t r; asm("cvt.rna.tf32.f32 %0, %1;" : "=r"(r) : "f"(x)); return r;
}
__device__ __forceinline__ void mma_tf32(float4& d,
    uint32_t a0, uint32_t a1, uint32_t a2, uint32_t a3,
    uint32_t b0, uint32_t b1)
{
    asm("mma.sync.aligned.m16n8k8.row.col.f32.tf32.tf32.f32 "
        "{%0,%1,%2,%3}, {%4,%5,%6,%7}, {%8,%9}, {%0,%1,%2,%3};"
        : "+f"(d.x), "+f"(d.y), "+f"(d.z), "+f"(d.w)
        : "r"(a0), "r"(a1), "r"(a2), "r"(a3), "r"(b0), "r"(b1));
}

// pack 8 k-values (j = k offset 0..7 of one column) into the fragment word
// order (word = (j&3)*2 + (j>>2)) and store as 2x STS.128 with the XOR-4
// halfblock swizzle (conflict-free across a warp of consecutive columns).
__device__ __forceinline__ void store_col8(uint32_t* dst, int n, const float* v) {
    uint4 A = make_uint4(f2tf(v[0]), f2tf(v[4]), f2tf(v[1]), f2tf(v[5]));
    uint4 B = make_uint4(f2tf(v[2]), f2tf(v[6]), f2tf(v[3]), f2tf(v[7]));
    if (n & 4) { ((uint4*)dst)[1] = A; ((uint4*)dst)[0] = B; }
    else       { ((uint4*)dst)[0] = A; ((uint4*)dst)[1] = B; }
}

__global__ __launch_bounds__(256, 2)
void autoint_kernel(const float* __restrict__ x,
                    const float* __restrict__ Wq, const float* __restrict__ bq,
                    const float* __restrict__ Wk, const float* __restrict__ bk,
                    const float* __restrict__ Wv, const float* __restrict__ bv,
                    const float* __restrict__ W1, const float* __restrict__ b1,
                    const float* __restrict__ W2, const float* __restrict__ b2,
                    float* __restrict__ out)
{
    extern __shared__ float sm[];
    float* axf = sm;
    float* kt  = sm + OFF_KT;
    float* qh  = sm + OFF_QH;
    float* vh  = sm + OFF_VH;
    float* att = sm + OFF_ATT;
    float* red = sm + OFF_RED;
    uint32_t* bst_u = (uint32_t*)att;    // tf32 B staging alias
    uint32_t* kt_u  = (uint32_t*)kt;

    const int t = threadIdx.x;
    const int b = blockIdx.x;
    const float* xg = x + (size_t)b * (NFEAT * DIM);

    const int lane = t & 31;
    const int grp  = lane >> 2;
    const int tig  = lane & 3;
    const int w    = t >> 5;
    const int mt   = w & 3;
    const int half = w >> 2;
    // hoisted swizzled B-consumption offset (uint32 words)
    const int lofs = (lane * 2) ^ ((lane & 16) >> 2);

    // ---- phase 0: x -> A-fragment order (fp32) ----
    {
        const float4* xg4 = (const float4*)xg;
#pragma unroll
        for (int n = t; n < NFEAT * DIM / 4; n += 256) {
            float4 v = xg4[n];
            int r   = n >> 6;
            int c4  = (n & 63) << 2;
            int rmt = r >> 4, rgr = r & 7, hi8 = (r >> 3) & 1;
            int ks  = c4 >> 3, chi = (c4 >> 2) & 1;
            float* d = axf + (((rmt * 32 + ks) * 32 + rgr * 4) << 2) + hi8 + (chi << 1);
            d[0]  = v.x;  d[4]  = v.y;  d[8]  = v.z;  d[12] = v.w;
        }
    }
    __syncthreads();

    const float inv_sqrt_d = 0.17677669529663687f;

    float4 facc4[16];
#pragma unroll
    for (int i = 0; i < 16; i++) facc4[i] = make_float4(0.f, 0.f, 0.f, 0.f);

    for (int h = 0; h < NHEAD; h++) {
        const int hd = h * HDIM;

        // ===== QKV projection: [64x96] = X @ [Wq|Wk|Wv][:,hd:hd+32]
        // 8 chunks of K=32; column-stager; warp tile m16 x n48.
        float4 D[6];
#pragma unroll
        for (int i = 0; i < 6; i++) D[i] = make_float4(0.f, 0.f, 0.f, 0.f);

        for (int ch = 0; ch < 8; ch++) {
            __syncthreads();            // staging buffer free
            if (t < 192) {              // stage 32k x 96n tf32
                const int n = t % 96, kslh = t / 96;
                const int mat = n >> 5;
                const float* W = (mat == 0) ? Wq : (mat == 1) ? Wk : Wv;
                const float* src = W + (ch * 32 + kslh * 16) * DIM + hd + (n & 31);
                float pv[16];
#pragma unroll
                for (int j = 0; j < 16; j++) pv[j] = src[j * DIM];
#pragma unroll
                for (int h8 = 0; h8 < 2; h8++) {
                    const int ksl = kslh * 2 + h8;
                    uint32_t* dst = bst_u + (ksl * 12 + (n >> 3)) * 64 + (n & 7) * 8;
                    store_col8(dst, n, pv + h8 * 8);
                }
            }
            __syncthreads();
#pragma unroll
            for (int ks2 = 0; ks2 < 4; ks2++) {
                float4 av = *(const float4*)&axf[((mt * 32 + ch * 4 + ks2) * 32 + lane) << 2];
                uint32_t a0 = f2tf(av.x), a1 = f2tf(av.y), a2 = f2tf(av.z), a3 = f2tf(av.w);
#pragma unroll
                for (int nt = 0; nt < 6; nt++) {
                    uint2 bb = *(const uint2*)&bst_u[(ks2 * 12 + half * 6 + nt) * 64 + lofs];
                    mma_tf32(D[nt], a0, a1, a2, a3, bb.x, bb.y);
                }
            }
        }
        // scatter D + bias into qh / kt / vh
        {
            const int r0 = mt * 16 + grp, r1 = r0 + 8;
#pragma unroll
            for (int nt = 0; nt < 6; nt++) {
                const int n   = half * 48 + nt * 8 + 2 * tig;
                const int mat = n >> 5;
                const int mc  = n & 31;
                const float* bp = (mat == 0) ? bq : (mat == 1) ? bk : bv;
                float2 bb = *(const float2*)&bp[hd + mc];
                float4 d = D[nt];
                if (mat == 0) {
                    *(float2*)&qh[r0 * QS + mc] = make_float2(d.x + bb.x, d.y + bb.y);
                    *(float2*)&qh[r1 * QS + mc] = make_float2(d.z + bb.x, d.w + bb.y);
                } else if (mat == 1) {
                    kt[mc * 64 + r0]       = d.x + bb.x;
                    kt[(mc + 1) * 64 + r0] = d.y + bb.y;
                    kt[mc * 64 + r1]       = d.z + bb.x;
                    kt[(mc + 1) * 64 + r1] = d.w + bb.y;
                } else {
                    *(float2*)&vh[r0 * HDIM + mc] = make_float2(d.x + bb.x, d.y + bb.y);
                    *(float2*)&vh[r1 * HDIM + mc] = make_float2(d.z + bb.x, d.w + bb.y);
                }
            }
        }
        __syncthreads();

        // ===== scores (fp32x2): att = q.k^T / sqrt(d)
        {
            const int i0 = (t >> 4) << 2;
            const int j0 = (t & 15) << 2;
            u64 a[4][2];
#pragma unroll
            for (int r = 0; r < 4; r++) { a[r][0] = 0ull; a[r][1] = 0ull; }
#pragma unroll
            for (int kk = 0; kk < HDIM; kk += 4) {
                ulonglong2 k0 = *(const ulonglong2*)&kt[(kk+0)*64 + j0];
                ulonglong2 k1 = *(const ulonglong2*)&kt[(kk+1)*64 + j0];
                ulonglong2 k2 = *(const ulonglong2*)&kt[(kk+2)*64 + j0];
                ulonglong2 k3 = *(const ulonglong2*)&kt[(kk+3)*64 + j0];
                float4 q0 = *(const float4*)&qh[(i0+0)*QS + kk];
                float4 q1 = *(const float4*)&qh[(i0+1)*QS + kk];
                float4 q2 = *(const float4*)&qh[(i0+2)*QS + kk];
                float4 q3 = *(const float4*)&qh[(i0+3)*QS + kk];
#pragma unroll
                for (int r = 0; r < 4; r++) {
                    float4 qr = (r==0) ? q0 : (r==1) ? q1 : (r==2) ? q2 : q3;
                    u64 d;
                    d = dup2(qr.x); ffma2(a[r][0], d, k0.x); ffma2(a[r][1], d, k0.y);
                    d = dup2(qr.y); ffma2(a[r][0], d, k1.x); ffma2(a[r][1], d, k1.y);
                    d = dup2(qr.z); ffma2(a[r][0], d, k2.x); ffma2(a[r][1], d, k2.y);
                    d = dup2(qr.w); ffma2(a[r][0], d, k3.x); ffma2(a[r][1], d, k3.y);
                }
            }
#pragma unroll
            for (int r = 0; r < 4; r++) {
                float2 lo = unpk(a[r][0]);
                float2 hi = unpk(a[r][1]);
                *(float4*)&att[(i0+r)*ATS + j0] = make_float4(
                    lo.x*inv_sqrt_d, lo.y*inv_sqrt_d, hi.x*inv_sqrt_d, hi.y*inv_sqrt_d);
            }
        }
        __syncthreads();

        // ---- softmax: 2 threads per row ----
        if (t < 128) {
            const int row = t >> 1;
            const int hf  = (t & 1) << 5;
            float* rp = att + row * ATS + hf;
            float m = rp[0];
#pragma unroll
            for (int j = 1; j < 32; j++) m = fmaxf(m, rp[j]);
            m = fmaxf(m, __shfl_xor_sync(0xFFFFFFFF, m, 1));
            float s = 0.f;
#pragma unroll
            for (int j = 0; j < 32; j++) { float e = __expf(rp[j] - m); rp[j] = e; s += e; }
            s += __shfl_xor_sync(0xFFFFFFFF, s, 1);
            float inv = 1.f / s;
#pragma unroll
            for (int j = 0; j < 32; j++) rp[j] *= inv;
        }
        __syncthreads();

        // ===== z = att @ vh  ->  kt as tf32 A-fragments (conflict-free)
        // 128 threads: thread owns rows (r0, r0+8) x cols c8..c8+7.
        if (t < 128) {
            const int ks4  = t & 3;
            const int grps = (t >> 2) & 7;
            const int rmts = t >> 5;
            const int r0 = rmts * 16 + grps, r1 = r0 + 8;
            const int c8 = ks4 * 8;
            u64 a0[4] = {0ull,0ull,0ull,0ull};
            u64 a1[4] = {0ull,0ull,0ull,0ull};
#pragma unroll 4
            for (int j = 0; j < NFEAT; j += 2) {
                float2 p0 = *(const float2*)&att[r0 * ATS + j];
                float2 p1 = *(const float2*)&att[r1 * ATS + j];
#pragma unroll
                for (int jj = 0; jj < 2; jj++) {
                    ulonglong2 vA = *(const ulonglong2*)&vh[(j+jj)*HDIM + c8];
                    ulonglong2 vB = *(const ulonglong2*)&vh[(j+jj)*HDIM + c8 + 4];
                    u64 d0 = dup2(jj ? p0.y : p0.x);
                    u64 d1 = dup2(jj ? p1.y : p1.x);
                    ffma2(a0[0], d0, vA.x); ffma2(a0[1], d0, vA.y);
                    ffma2(a0[2], d0, vB.x); ffma2(a0[3], d0, vB.y);
                    ffma2(a1[0], d1, vA.x); ffma2(a1[1], d1, vA.y);
                    ffma2(a1[2], d1, vB.x); ffma2(a1[3], d1, vB.y);
                }
            }
            float z0[8], z1[8];
#pragma unroll
            for (int q = 0; q < 4; q++) {
                float2 f0 = unpk(a0[q]); z0[2*q] = f0.x; z0[2*q+1] = f0.y;
                float2 f1 = unpk(a1[q]); z1[2*q] = f1.x; z1[2*q+1] = f1.y;
            }
            const uint32_t base = (rmts * 4 + ks4) * 128 + grps * 16;
#pragma unroll
            for (int i = 0; i < 4; i++) {
                uint4 val = make_uint4(f2tf(z0[i]), f2tf(z1[i]),
                                       f2tf(z0[i+4]), f2tf(z1[i+4]));
                *(uint4*)&kt_u[base + ((i ^ ks4) << 2)] = val;
            }
        }
        __syncthreads();   // z fragments visible; att (bst) free

        // ===== facc += z @ W1[hd:hd+32,:]  (2 chunks of 128 n)
        for (int nc = 0; nc < 2; nc++) {
            if (nc) __syncthreads();   // prev compute done reading bst
            {   // stage 32k x 128n (column stager, all 256 threads)
                const int n = t & 127, kslh = t >> 7;
                const float* src = W1 + (hd + kslh * 16) * DIM + nc * 128 + n;
                float wv[16];
#pragma unroll
                for (int j = 0; j < 16; j++) wv[j] = src[j * DIM];
#pragma unroll
                for (int h8 = 0; h8 < 2; h8++) {
                    const int ksl = kslh * 2 + h8;
                    uint32_t* dst = bst_u + (ksl * 16 + (n >> 3)) * 64 + (n & 7) * 8;
                    store_col8(dst, n, wv + h8 * 8);
                }
            }
            __syncthreads();
#pragma unroll
            for (int ks = 0; ks < 4; ks++) {
                uint4 za = *(const uint4*)&kt_u[(mt * 4 + ks) * 128 + grp * 16
                                                + ((tig ^ ks) << 2)];
#pragma unroll
                for (int nt = 0; nt < 8; nt++) {
                    uint2 bb = *(const uint2*)&bst_u[(ks * 16 + half * 8 + nt) * 64 + lofs];
                    mma_tf32(facc4[nc * 8 + nt], za.x, za.y, za.z, za.w, bb.x, bb.y);
                }
            }
        }
        // next head's proj loop first sync protects bst/kt reuse
    }

    // ===== epilogue: f = relu(facc + b1 + x); dot W2 =====
    {
        const int r0 = mt * 16 + grp, r1 = r0 + 8;
        float part = 0.f;
#pragma unroll
        for (int fi = 0; fi < 16; fi++) {
            int nc = fi >> 3, nt = fi & 7;
            int n  = nc * 128 + half * 64 + nt * 8 + 2 * tig;
            float2 b1v = *(const float2*)&b1[n];
            int ksa = n >> 3;
            int tga = n & 3, chia = (n >> 2) & 1;
            int tgb = (n + 1) & 3, chib = ((n + 1) >> 2) & 1;
            const float* pa = &axf[(((mt * 32 + ksa) * 32 + grp * 4 + tga)) << 2];
            const float* pb = &axf[(((mt * 32 + ksa) * 32 + grp * 4 + tgb)) << 2];
            float x00 = pa[(chia << 1)];
            float x10 = pa[(chia << 1) + 1];
            float x01 = pb[(chib << 1)];
            float x11 = pb[(chib << 1) + 1];
            float2 w20 = *(const float2*)&W2[r0 * DIM + n];
            float2 w21 = *(const float2*)&W2[r1 * DIM + n];
            float4 d = facc4[fi];
            float f0 = fmaxf(d.x + b1v.x + x00, 0.f);
            float f1 = fmaxf(d.y + b1v.y + x01, 0.f);
            float f2 = fmaxf(d.z + b1v.x + x10, 0.f);
            float f3 = fmaxf(d.w + b1v.y + x11, 0.f);
            part += f0 * w20.x + f1 * w20.y + f2 * w21.x + f3 * w21.y;
        }
        red[t] = part;
    }
    __syncthreads();

#pragma unroll
    for (int s = 128; s > 0; s >>= 1) {
        if (t < s) red[t] += red[t + s];
        __syncthreads();
    }
    if (t == 0) {
        out[b] = 1.f / (1.f + __expf(-(red[0] + b2[0])));
    }
}

extern "C" void kernel_launch(void* const* d_in, const int* in_sizes, int n_in,
                              void* d_out, int out_size)
{
    const float* x  = (const float*)d_in[0];
    const float* Wq = (const float*)d_in[1];
    const float* bq = (const float*)d_in[2];
    const float* Wk = (const float*)d_in[3];
    const float* bk = (const float*)d_in[4];
    const float* Wv = (const float*)d_in[5];
    const float* bv = (const float*)d_in[6];
    const float* W1 = (const float*)d_in[7];
    const float* b1 = (const float*)d_in[8];
    const float* W2 = (const float*)d_in[9];
    const float* b2 = (const float*)d_in[10];
    float* out = (float*)d_out;

    const int smem_bytes = SMEM_FLOATS * (int)sizeof(float); // 109,568 B -> 2 CTAs/SM
    cudaFuncSetAttribute(autoint_kernel,
                         cudaFuncAttributeMaxDynamicSharedMemorySize, smem_bytes);

    autoint_kernel<<<8192, 256, smem_bytes>>>(x, Wq, bq, Wk, bk, Wv, bv,
                                              W1, b1, W2, b2, out);
}